// round 6
// baseline (speedup 1.0000x reference)
#include <cuda_runtime.h>

#define N_NODES 100000
#define N_EDGES 1600000
#define IN_CH   128
#define HID_CH  64
#define OUT_CH  40
#define SCAN_B  1024
#define SCAN_NB ((N_NODES + SCAN_B - 1) / SCAN_B)   // 98

// ---------------- scratch (static device globals; no allocation) ----------------
__device__ float g_h[N_NODES * 64];      // GEMM output of current layer (stride 64)
__device__ float g_a[N_NODES * 64];      // layer-1 aggregated/activated
__device__ float g_b[N_NODES * 64];      // layer-2 aggregated/activated
__device__ float g_dis[N_NODES];         // (deg+1)^-1/2
__device__ int   g_cnt[N_NODES];         // in-degree (excl. self-loop)
__device__ int   g_rs[N_NODES];          // CSR row start (exclusive scan of cnt)
__device__ int   g_cur[N_NODES];         // CSR fill cursors
__device__ int   g_col[N_EDGES];         // CSR src indices
__device__ float g_wn[N_EDGES];          // CSR per-edge norm
__device__ int   g_bsum[SCAN_NB];        // scan block sums
__device__ float g_w3p[64 * 64];         // W3 zero-padded to 64 cols

static inline int cdiv_i(long long a, int b) { return (int)((a + b - 1) / b); }

// ---------------- prep: degree / dis / CSR ----------------
__global__ void cnt_zero_kernel() {
    int i = blockIdx.x * blockDim.x + threadIdx.x;
    if (i < N_NODES) { g_cnt[i] = 0; g_cur[i] = 0; }
}

__global__ void deg_count_kernel(const int* __restrict__ ei) {
    int e = blockIdx.x * blockDim.x + threadIdx.x;
    if (e < N_EDGES) atomicAdd(&g_cnt[ei[N_EDGES + e]], 1);
}

__global__ void dis_kernel() {
    int i = blockIdx.x * blockDim.x + threadIdx.x;
    if (i < N_NODES) g_dis[i] = rsqrtf((float)(g_cnt[i] + 1));  // +1 self-loop
}

// exclusive scan of g_cnt into g_rs (3-phase blocked scan)
__global__ void scan_block_kernel() {
    __shared__ int sm[SCAN_B];
    int i = blockIdx.x * SCAN_B + threadIdx.x;
    int v = (i < N_NODES) ? g_cnt[i] : 0;
    sm[threadIdx.x] = v;
    __syncthreads();
    for (int off = 1; off < SCAN_B; off <<= 1) {
        int t = (threadIdx.x >= off) ? sm[threadIdx.x - off] : 0;
        __syncthreads();
        sm[threadIdx.x] += t;
        __syncthreads();
    }
    if (i < N_NODES) g_rs[i] = sm[threadIdx.x] - v;  // exclusive
    if (threadIdx.x == SCAN_B - 1) g_bsum[blockIdx.x] = sm[threadIdx.x];
}

__global__ void scan_sums_kernel() {
    if (threadIdx.x == 0 && blockIdx.x == 0) {
        int acc = 0;
        for (int i = 0; i < SCAN_NB; i++) { int t = g_bsum[i]; g_bsum[i] = acc; acc += t; }
    }
}

__global__ void scan_add_kernel() {
    int i = blockIdx.x * SCAN_B + threadIdx.x;
    if (i < N_NODES) g_rs[i] += g_bsum[blockIdx.x];
}

__global__ void fill_csr_kernel(const int* __restrict__ ei) {
    int e = blockIdx.x * blockDim.x + threadIdx.x;
    if (e >= N_EDGES) return;
    int s = ei[e];
    int d = ei[N_EDGES + e];
    int p = g_rs[d] + atomicAdd(&g_cur[d], 1);
    g_col[p] = s;
    g_wn[p] = g_dis[s] * g_dis[d];
}

__global__ void padw3_kernel(const float* __restrict__ w3) {
    int i = blockIdx.x * blockDim.x + threadIdx.x;
    if (i < 64 * 64) {
        int r = i >> 6, c = i & 63;
        g_w3p[i] = (c < OUT_CH) ? w3[r * OUT_CH + c] : 0.0f;
    }
}

// ---------------- GEMM: g_h[n][64] = X[n][CIN] @ W[CIN][64] ----------------
// SELX: 0 = external pointer, 1 = g_a, 2 = g_b.  SELW: 0 = external, 1 = g_w3p.
template <int CIN, int SELX, int SELW>
__global__ void gemm64_kernel(const float* __restrict__ Xext,
                              const float* __restrict__ Wext, int nrows) {
    __shared__ float Xs[16 * 68];  // [k][row], padded stride
    __shared__ float Ws[16 * 64];  // [k][col]

    const float* X = (SELX == 0) ? Xext : (SELX == 1) ? (const float*)g_a
                                                      : (const float*)g_b;
    const float* W = (SELW == 0) ? Wext : (const float*)g_w3p;
    float* H = g_h;

    const int tid = threadIdx.x;              // 0..127
    const int blockRow = blockIdx.x * 64;
    const int tx = tid & 15, ty = tid >> 4;
    const int col0 = tx * 4, row0 = ty * 8;

    float acc[8][4];
#pragma unroll
    for (int i = 0; i < 8; i++)
#pragma unroll
        for (int j = 0; j < 4; j++) acc[i][j] = 0.0f;

    for (int k0 = 0; k0 < CIN; k0 += 16) {
        {   // X tile (64 rows x 16 k), transposed into Xs[k][row]
            int k4 = tid & 3;
            int r  = tid >> 2;
#pragma unroll
            for (int rr = 0; rr < 2; rr++) {
                int row = r + rr * 32;
                int grow = blockRow + row;
                float4 v = make_float4(0.f, 0.f, 0.f, 0.f);
                if (grow < nrows)
                    v = *(const float4*)&X[(long long)grow * CIN + k0 + k4 * 4];
                Xs[(k4 * 4 + 0) * 68 + row] = v.x;
                Xs[(k4 * 4 + 1) * 68 + row] = v.y;
                Xs[(k4 * 4 + 2) * 68 + row] = v.z;
                Xs[(k4 * 4 + 3) * 68 + row] = v.w;
            }
        }
        {   // W tile (16 k x 64 cols)
            int c4 = tid & 15, kk = tid >> 4;
#pragma unroll
            for (int rr = 0; rr < 2; rr++) {
                int k = kk + rr * 8;
                *(float4*)&Ws[k * 64 + c4 * 4] =
                    *(const float4*)&W[(long long)(k0 + k) * 64 + c4 * 4];
            }
        }
        __syncthreads();

#pragma unroll
        for (int k = 0; k < 16; k++) {
            float4 w  = *(float4*)&Ws[k * 64 + col0];
            float4 xa = *(float4*)&Xs[k * 68 + row0];
            float4 xb = *(float4*)&Xs[k * 68 + row0 + 4];
            float xv[8] = {xa.x, xa.y, xa.z, xa.w, xb.x, xb.y, xb.z, xb.w};
#pragma unroll
            for (int i = 0; i < 8; i++) {
                acc[i][0] += xv[i] * w.x;
                acc[i][1] += xv[i] * w.y;
                acc[i][2] += xv[i] * w.z;
                acc[i][3] += xv[i] * w.w;
            }
        }
        __syncthreads();
    }

#pragma unroll
    for (int i = 0; i < 8; i++) {
        int grow = blockRow + row0 + i;
        if (grow < nrows)
            *(float4*)&H[(long long)grow * 64 + col0] =
                make_float4(acc[i][0], acc[i][1], acc[i][2], acc[i][3]);
    }
}

// ---------------- gather aggregation: one warp per node ----------------
// out[d][c] = sum_{e in CSR(d)} h[src_e][c]*wn_e + h[d][c]*dis[d]^2, then bias(+relu)
// SELOUT: 1 = g_a, 2 = g_b
template <int SELOUT>
__global__ void gather64_kernel(const float* __restrict__ bias) {
    int w = (blockIdx.x * blockDim.x + threadIdx.x) >> 5;
    int lane = threadIdx.x & 31;
    if (w >= N_NODES) return;
    const float* H = g_h;
    float* O = (SELOUT == 1) ? g_a : g_b;

    int beg = g_rs[w], n = g_cnt[w];
    float a0 = 0.0f, a1 = 0.0f;
    for (int j = 0; j < n; j++) {
        int s   = g_col[beg + j];
        float t = g_wn[beg + j];
        a0 = fmaf(H[s * 64 + lane],      t, a0);
        a1 = fmaf(H[s * 64 + lane + 32], t, a1);
    }
    float d = g_dis[w];
    float dsq = d * d;
    a0 = fmaf(H[w * 64 + lane],      dsq, a0);
    a1 = fmaf(H[w * 64 + lane + 32], dsq, a1);
    O[w * 64 + lane]      = fmaxf(a0 + bias[lane], 0.0f);
    O[w * 64 + lane + 32] = fmaxf(a1 + bias[lane + 32], 0.0f);
}

// final layer: gather (40 valid cols, h padded to 64 w/ zero cols) + bias + log_softmax
__global__ void gather40_lsm_kernel(const float* __restrict__ b3, float* __restrict__ out) {
    int w = (blockIdx.x * blockDim.x + threadIdx.x) >> 5;
    int lane = threadIdx.x & 31;
    if (w >= N_NODES) return;
    const float* H = g_h;
    bool p1 = (lane < OUT_CH - 32);   // lanes 0..7

    int beg = g_rs[w], n = g_cnt[w];
    float a0 = 0.0f, a1 = 0.0f;
    for (int j = 0; j < n; j++) {
        int s   = g_col[beg + j];
        float t = g_wn[beg + j];
        a0 = fmaf(H[s * 64 + lane],      t, a0);   // padded cols are exactly 0
        a1 = fmaf(H[s * 64 + lane + 32], t, a1);
    }
    float d = g_dis[w];
    float dsq = d * d;
    a0 = fmaf(H[w * 64 + lane],      dsq, a0);
    a1 = fmaf(H[w * 64 + lane + 32], dsq, a1);

    float v0 = a0 + b3[lane];                       // lane < 32 < 40 always valid
    float v1 = p1 ? (a1 + b3[lane + 32]) : -1e30f;

    float m = fmaxf(v0, v1);
#pragma unroll
    for (int o = 16; o; o >>= 1) m = fmaxf(m, __shfl_xor_sync(0xffffffffu, m, o));
    float s = expf(v0 - m) + (p1 ? expf(v1 - m) : 0.0f);
#pragma unroll
    for (int o = 16; o; o >>= 1) s += __shfl_xor_sync(0xffffffffu, s, o);
    float ls = logf(s);

    float* r = out + (long long)w * OUT_CH;
    r[lane] = v0 - m - ls;
    if (p1) r[lane + 32] = v1 - m - ls;
}

// ---------------- launch ----------------
extern "C" void kernel_launch(void* const* d_in, const int* in_sizes, int n_in,
                              void* d_out, int out_size) {
    const float* x  = (const float*)d_in[0];
    const int*   ei = (const int*)d_in[1];     // int32! (JAX x64 disabled)
    const float* W1 = (const float*)d_in[2];
    const float* b1 = (const float*)d_in[3];
    const float* W2 = (const float*)d_in[4];
    const float* b2 = (const float*)d_in[5];
    const float* W3 = (const float*)d_in[6];
    const float* b3 = (const float*)d_in[7];
    float* out = (float*)d_out;

    const int T = 256;

    // ---- CSR / norm prep ----
    cnt_zero_kernel<<<cdiv_i(N_NODES, T), T>>>();
    deg_count_kernel<<<cdiv_i(N_EDGES, T), T>>>(ei);
    dis_kernel<<<cdiv_i(N_NODES, T), T>>>();
    scan_block_kernel<<<SCAN_NB, SCAN_B>>>();
    scan_sums_kernel<<<1, 32>>>();
    scan_add_kernel<<<SCAN_NB, SCAN_B>>>();
    fill_csr_kernel<<<cdiv_i(N_EDGES, T), T>>>(ei);
    padw3_kernel<<<cdiv_i(64 * 64, T), T>>>(W3);

    const int gemm_blocks   = cdiv_i(N_NODES, 64);
    const int gather_blocks = cdiv_i((long long)N_NODES * 32, T);

    // ---- layer 1: 128 -> 64, relu ----
    gemm64_kernel<IN_CH, 0, 0><<<gemm_blocks, 128>>>(x, W1, N_NODES);
    gather64_kernel<1><<<gather_blocks, T>>>(b1);

    // ---- layer 2: 64 -> 64, relu ----
    gemm64_kernel<HID_CH, 1, 0><<<gemm_blocks, 128>>>(nullptr, W2, N_NODES);
    gather64_kernel<2><<<gather_blocks, T>>>(b2);

    // ---- layer 3: 64 -> 40 (padded), bias + log_softmax fused ----
    gemm64_kernel<HID_CH, 2, 1><<<gemm_blocks, 128>>>(nullptr, nullptr, N_NODES);
    gather40_lsm_kernel<<<gather_blocks, T>>>(b3, out);
}